// round 3
// baseline (speedup 1.0000x reference)
#include <cuda_runtime.h>
#include <math.h>

#define D_    256
#define HW_   1024
#define N_    32768
#define K_    1024
#define NELEM_ 8388608

#define BT    128
#define BK    256
#define DC    16
#define EPITCH 132
#define EPSM  3e-4f

// -------- device scratch --------
__device__ float g_dist[N_ * (size_t)K_];   // 128 MiB approx distances (minus ||x||^2)
__device__ float g_B[K_];                   // fl32(f64 sum e^2)
__device__ int   g_idx[N_];
__device__ int   g_counts[K_];
__device__ float g_partials[N_ / BT];

// ---------------------------------------------------------
__global__ void init_kernel() {
    int i = blockIdx.x * blockDim.x + threadIdx.x;
    if (i < K_) g_counts[i] = 0;
}

__global__ void enorm_kernel(const float* __restrict__ E) {
    __shared__ double red[256];
    int k = blockIdx.x;
    float v = E[(size_t)k * D_ + threadIdx.x];
    red[threadIdx.x] = (double)v * (double)v;
    __syncthreads();
    for (int s = 128; s > 0; s >>= 1) {
        if (threadIdx.x < s) red[threadIdx.x] += red[threadIdx.x + s];
        __syncthreads();
    }
    if (threadIdx.x == 0) g_B[k] = (float)red[0];
}

// ---------------------------------------------------------
// Phase 1: approx distances d~ = ||e||^2 - 2 x.e  (fp32, f32x2-packed FMA)
__global__ void __launch_bounds__(256, 1)
dist_kernel(const float* __restrict__ IN, const float* __restrict__ E) {
    extern __shared__ float smem[];
    float* xs = smem;                 // [256][128]
    float* es = smem + D_ * BT;       // [DC][EPITCH]

    const int tid = threadIdx.x;
    const int tx  = tid & 15;
    const int ty  = tid >> 4;

    const int n0  = blockIdx.x * BT;
    const int b   = n0 >> 10;
    const int hw0 = n0 & (HW_ - 1);
    const float* inb = IN + (size_t)b * (D_ * HW_) + hw0;

    #pragma unroll
    for (int it = 0; it < 32; ++it) {
        int j  = it * 256 + tid;
        int t4 = j & 31;
        int d  = j >> 5;
        float4 v = *reinterpret_cast<const float4*>(inb + (size_t)d * HW_ + t4 * 4);
        *reinterpret_cast<float4*>(&xs[d * BT + t4 * 4]) = v;
    }

    const int k0 = blockIdx.y * BK;

    for (int kt = 0; kt < BK / 128; ++kt) {
        const int kb = k0 + kt * 128;
        unsigned long long acc[4][8];
        #pragma unroll
        for (int i = 0; i < 4; ++i)
            #pragma unroll
            for (int j = 0; j < 8; ++j) acc[i][j] = 0ull;

        float4 r0, r1;
        {
            const float* base = E + (size_t)kb * D_;
            int f0 = tid, f1 = tid + 256;
            r0 = *reinterpret_cast<const float4*>(base + (size_t)(f0 >> 2) * D_ + (f0 & 3) * 4);
            r1 = *reinterpret_cast<const float4*>(base + (size_t)(f1 >> 2) * D_ + (f1 & 3) * 4);
        }

        for (int dc = 0; dc < D_ / DC; ++dc) {
            __syncthreads();
            {
                int f0 = tid, f1 = tid + 256;
                int d40 = (f0 & 3) * 4, kk0 = f0 >> 2;
                es[(d40 + 0) * EPITCH + kk0] = r0.x;
                es[(d40 + 1) * EPITCH + kk0] = r0.y;
                es[(d40 + 2) * EPITCH + kk0] = r0.z;
                es[(d40 + 3) * EPITCH + kk0] = r0.w;
                int d41 = (f1 & 3) * 4, kk1 = f1 >> 2;
                es[(d41 + 0) * EPITCH + kk1] = r1.x;
                es[(d41 + 1) * EPITCH + kk1] = r1.y;
                es[(d41 + 2) * EPITCH + kk1] = r1.z;
                es[(d41 + 3) * EPITCH + kk1] = r1.w;
            }
            if (dc + 1 < D_ / DC) {
                const float* base = E + (size_t)kb * D_ + (dc + 1) * DC;
                int f0 = tid, f1 = tid + 256;
                r0 = *reinterpret_cast<const float4*>(base + (size_t)(f0 >> 2) * D_ + (f0 & 3) * 4);
                r1 = *reinterpret_cast<const float4*>(base + (size_t)(f1 >> 2) * D_ + (f1 & 3) * 4);
            }
            __syncthreads();

            #pragma unroll
            for (int d = 0; d < DC; ++d) {
                const float* xr = &xs[(dc * DC + d) * BT + ty * 8];
                ulonglong2 a01 = *reinterpret_cast<const ulonglong2*>(xr);
                ulonglong2 a23 = *reinterpret_cast<const ulonglong2*>(xr + 4);
                unsigned long long a2[4] = {a01.x, a01.y, a23.x, a23.y};
                const float* er = &es[d * EPITCH + tx * 8];
                float4 bl = *reinterpret_cast<const float4*>(er);
                float4 bh = *reinterpret_cast<const float4*>(er + 4);
                unsigned long long bb[8];
                asm("mov.b64 %0,{%1,%1};" : "=l"(bb[0]) : "r"(__float_as_uint(bl.x)));
                asm("mov.b64 %0,{%1,%1};" : "=l"(bb[1]) : "r"(__float_as_uint(bl.y)));
                asm("mov.b64 %0,{%1,%1};" : "=l"(bb[2]) : "r"(__float_as_uint(bl.z)));
                asm("mov.b64 %0,{%1,%1};" : "=l"(bb[3]) : "r"(__float_as_uint(bl.w)));
                asm("mov.b64 %0,{%1,%1};" : "=l"(bb[4]) : "r"(__float_as_uint(bh.x)));
                asm("mov.b64 %0,{%1,%1};" : "=l"(bb[5]) : "r"(__float_as_uint(bh.y)));
                asm("mov.b64 %0,{%1,%1};" : "=l"(bb[6]) : "r"(__float_as_uint(bh.z)));
                asm("mov.b64 %0,{%1,%1};" : "=l"(bb[7]) : "r"(__float_as_uint(bh.w)));
                #pragma unroll
                for (int i2 = 0; i2 < 4; ++i2)
                    #pragma unroll
                    for (int j = 0; j < 8; ++j)
                        asm("fma.rn.f32x2 %0, %1, %2, %0;"
                            : "+l"(acc[i2][j]) : "l"(a2[i2]), "l"(bb[j]));
            }
        }

        // write d~ tile to global
        float en[8];
        #pragma unroll
        for (int j = 0; j < 8; ++j) en[j] = __ldg(&g_B[kb + tx * 8 + j]);
        #pragma unroll
        for (int i2 = 0; i2 < 4; ++i2) {
            float v0[8], v1[8];
            #pragma unroll
            for (int j = 0; j < 8; ++j) {
                unsigned long long v = acc[i2][j];
                v0[j] = fmaf(-2.0f, __uint_as_float((unsigned)v), en[j]);
                v1[j] = fmaf(-2.0f, __uint_as_float((unsigned)(v >> 32)), en[j]);
            }
            int t0 = n0 + ty * 8 + 2 * i2;
            float* p0 = g_dist + (size_t)t0 * K_ + kb + tx * 8;
            *reinterpret_cast<float4*>(p0)     = make_float4(v0[0], v0[1], v0[2], v0[3]);
            *reinterpret_cast<float4*>(p0 + 4) = make_float4(v0[4], v0[5], v0[6], v0[7]);
            float* p1 = p0 + K_;
            *reinterpret_cast<float4*>(p1)     = make_float4(v1[0], v1[1], v1[2], v1[3]);
            *reinterpret_cast<float4*>(p1 + 4) = make_float4(v1[4], v1[5], v1[6], v1[7]);
        }
    }
}

// ---------------------------------------------------------
__device__ __forceinline__ unsigned order_f(float f) {
    unsigned u = __float_as_uint(f);
    return (u & 0x80000000u) ? ~u : (u | 0x80000000u);
}

// Phase 2: per-token argmin with exact emulation of reference fp32 rounding
// dist_ref = fl32( fl32(A + B_k) - 2*fl32(dot) ), ties -> smallest k.
__global__ void __launch_bounds__(256, 2)
select_kernel(const float* __restrict__ IN, const float* __restrict__ E) {
    const int warp = threadIdx.x >> 5;
    const int lane = threadIdx.x & 31;
    const int n = blockIdx.x * 8 + warp;

    const float* dr = g_dist + (size_t)n * K_;
    float vals[32];
    float m = 3.4e38f;
    #pragma unroll
    for (int j = 0; j < 32; ++j) {
        float v = dr[lane + 32 * j];
        vals[j] = v;
        m = fminf(m, v);
    }
    #pragma unroll
    for (int off = 16; off > 0; off >>= 1)
        m = fminf(m, __shfl_xor_sync(0xFFFFFFFFu, m, off));
    const float thresh = m + EPSM;

    int local = 0;
    #pragma unroll
    for (int j = 0; j < 32; ++j) local += (vals[j] <= thresh);
    int tot = local;
    #pragma unroll
    for (int off = 16; off > 0; off >>= 1)
        tot += __shfl_xor_sync(0xFFFFFFFFu, tot, off);

    unsigned long long key = 0xFFFFFFFFFFFFFFFFull;
    const int b = n >> 10, hw = n & (HW_ - 1);
    const float* xb = IN + (size_t)b * (D_ * HW_) + hw;

    if (tot == 1) {
        #pragma unroll
        for (int j = 0; j < 32; ++j)
            if (vals[j] <= thresh) {
                int k = lane + 32 * j;
                key = ((unsigned long long)order_f(vals[j]) << 32) | (unsigned)k;
            }
    } else {
        // A = fl32(f64 sum x^2)
        double a = 0.0;
        #pragma unroll
        for (int d = lane; d < D_; d += 32) {
            double x = (double)xb[(size_t)d * HW_];
            a += x * x;
        }
        #pragma unroll
        for (int off = 16; off > 0; off >>= 1)
            a += __shfl_xor_sync(0xFFFFFFFFu, a, off);
        float Af = (float)a;

        #pragma unroll
        for (int j = 0; j < 32; ++j) {
            if (vals[j] <= thresh) {
                int k = lane + 32 * j;
                const float* er = E + (size_t)k * D_;
                double dot = 0.0;
                for (int d = 0; d < D_; ++d)
                    dot += (double)xb[(size_t)d * HW_] * (double)er[d];
                float Mf = (float)dot;
                float T  = Af + __ldg(&g_B[k]);   // fl32
                float ds = T - 2.0f * Mf;         // fl32
                unsigned long long kk =
                    ((unsigned long long)order_f(ds) << 32) | (unsigned)k;
                if (kk < key) key = kk;
            }
        }
    }
    #pragma unroll
    for (int off = 16; off > 0; off >>= 1) {
        unsigned long long o = __shfl_xor_sync(0xFFFFFFFFu, key, off);
        if (o < key) key = o;
    }
    if (lane == 0) {
        int k = (int)(unsigned)key;
        g_idx[n] = k;
        atomicAdd(&g_counts[k], 1);
    }
}

// ---------------------------------------------------------
__global__ void __launch_bounds__(256, 1)
gather_kernel(const float* __restrict__ IN, const float* __restrict__ E,
              float* __restrict__ OUT) {
    extern __shared__ float smem[];
    float* qs   = smem;                          // [128][257]
    int*   sidx = (int*)(smem + 128 * 257);
    float* red  = smem + 128 * 257 + 128;

    const int tid = threadIdx.x;
    const int n0  = blockIdx.x * BT;

    if (tid < BT) sidx[tid] = g_idx[n0 + tid];
    __syncthreads();

    #pragma unroll 4
    for (int it = 0; it < BT; ++it)
        qs[it * 257 + tid] = E[(size_t)sidx[it] * D_ + tid];
    __syncthreads();

    const int b = n0 >> 10, hw0 = n0 & (HW_ - 1);
    const size_t base = (size_t)b * (D_ * HW_) + hw0;
    float lsum = 0.0f;
    #pragma unroll 4
    for (int it = 0; it < 128; ++it) {
        int j = it * 256 + tid;
        int d = j >> 7;
        int t = j & 127;
        size_t a = base + (size_t)d * HW_ + t;
        float x = IN[a];
        float q = qs[t * 257 + d];
        OUT[a] = q;
        float df = q - x;
        lsum += df * df;
    }
    red[tid] = lsum;
    __syncthreads();
    for (int s = 128; s > 0; s >>= 1) {
        if (tid < s) red[tid] += red[tid + s];
        __syncthreads();
    }
    if (tid == 0) g_partials[blockIdx.x] = red[0];
}

// ---------------------------------------------------------
__global__ void finalize_kernel(float* __restrict__ OUT, int out_size) {
    __shared__ float red[256];
    int tid = threadIdx.x;

    red[tid] = g_partials[tid];
    __syncthreads();
    for (int s = 128; s > 0; s >>= 1) {
        if (tid < s) red[tid] += red[tid + s];
        __syncthreads();
    }
    float loss = 1.25f * red[0] / (float)NELEM_;
    __syncthreads();

    float ps = 0.0f;
    for (int i = tid; i < K_; i += 256) {
        float p = (float)g_counts[i] / (float)N_;
        ps += p * logf(p + 1e-10f);
    }
    red[tid] = ps;
    __syncthreads();
    for (int s = 128; s > 0; s >>= 1) {
        if (tid < s) red[tid] += red[tid + s];
        __syncthreads();
    }
    if (tid == 0) {
        float perp = expf(-red[0]);
        if (out_size > NELEM_)     OUT[NELEM_]     = loss;
        if (out_size > NELEM_ + 1) OUT[NELEM_ + 1] = perp;
    }
}

// ---------------------------------------------------------
extern "C" void kernel_launch(void* const* d_in, const int* in_sizes, int n_in,
                              void* d_out, int out_size) {
    const float* IN = (const float*)d_in[0];
    const float* E  = (const float*)d_in[1];
    float* OUT = (float*)d_out;

    const int smemB = (D_ * BT + DC * EPITCH) * (int)sizeof(float);
    const int smemC = (128 * 257 + 128 + 256) * (int)sizeof(float);
    cudaFuncSetAttribute(dist_kernel,   cudaFuncAttributeMaxDynamicSharedMemorySize, smemB);
    cudaFuncSetAttribute(gather_kernel, cudaFuncAttributeMaxDynamicSharedMemorySize, smemC);

    init_kernel<<<4, 256>>>();
    enorm_kernel<<<K_, 256>>>(E);
    dist_kernel<<<dim3(N_ / BT, K_ / BK), 256, smemB>>>(IN, E);
    select_kernel<<<N_ / 8, 256>>>(IN, E);   // FIX: one token per warp, 8 warps/block
    gather_kernel<<<N_ / BT, 256, smemC>>>(IN, E, OUT);
    finalize_kernel<<<1, 256>>>(OUT, out_size);
}

// round 4
// speedup vs baseline: 1.0545x; 1.0545x over previous
#include <cuda_runtime.h>
#include <math.h>

#define D_    256
#define HW_   1024
#define N_    32768
#define K_    1024
#define NELEM_ 8388608

#define BT    128
#define BK    256
#define DC    16
#define EPITCH 132
#define EPSM  3e-4f

// -------- device scratch --------
__device__ float g_dist[N_ * (size_t)K_];   // 128 MiB approx distances (minus ||x||^2)
__device__ float g_B[K_];                   // fl32(f64 sum e^2)
__device__ int   g_idx[N_];
__device__ int   g_counts[K_];
__device__ float g_partials[N_ / BT];

// ---------------------------------------------------------
__global__ void init_kernel() {
    int i = blockIdx.x * blockDim.x + threadIdx.x;
    if (i < K_) g_counts[i] = 0;
}

__global__ void enorm_kernel(const float* __restrict__ E) {
    __shared__ double red[256];
    int k = blockIdx.x;
    float v = E[(size_t)k * D_ + threadIdx.x];
    red[threadIdx.x] = (double)v * (double)v;
    __syncthreads();
    for (int s = 128; s > 0; s >>= 1) {
        if (threadIdx.x < s) red[threadIdx.x] += red[threadIdx.x + s];
        __syncthreads();
    }
    if (threadIdx.x == 0) g_B[k] = (float)red[0];
}

// ---------------------------------------------------------
// Phase 1: approx distances d~ = ||e||^2 - 2 x.e  (fp32, f32x2-packed FMA)
// es double-buffered: STS of chunk dc+1 overlaps FFMA of chunk dc.
__global__ void __launch_bounds__(256, 1)
dist_kernel(const float* __restrict__ IN, const float* __restrict__ E) {
    extern __shared__ float smem[];
    float* xs  = smem;                        // [256][128]
    float* es0 = smem + D_ * BT;              // [DC][EPITCH]
    float* es1 = es0 + DC * EPITCH;           // [DC][EPITCH]

    const int tid = threadIdx.x;
    const int tx  = tid & 15;
    const int ty  = tid >> 4;

    const int n0  = blockIdx.x * BT;
    const int b   = n0 >> 10;
    const int hw0 = n0 & (HW_ - 1);
    const float* inb = IN + (size_t)b * (D_ * HW_) + hw0;

    #pragma unroll
    for (int it = 0; it < 32; ++it) {
        int j  = it * 256 + tid;
        int t4 = j & 31;
        int d  = j >> 5;
        float4 v = *reinterpret_cast<const float4*>(inb + (size_t)d * HW_ + t4 * 4);
        *reinterpret_cast<float4*>(&xs[d * BT + t4 * 4]) = v;
    }

    const int k0 = blockIdx.y * BK;
    const int f0 = tid, f1 = tid + 256;
    const int d40 = (f0 & 3) * 4, kk0 = f0 >> 2;
    const int d41 = (f1 & 3) * 4, kk1 = f1 >> 2;

    for (int kt = 0; kt < BK / 128; ++kt) {
        const int kb = k0 + kt * 128;
        unsigned long long acc[4][8];
        #pragma unroll
        for (int i = 0; i < 4; ++i)
            #pragma unroll
            for (int j = 0; j < 8; ++j) acc[i][j] = 0ull;

        const float* ebase = E + (size_t)kb * D_;
        float4 r0 = *reinterpret_cast<const float4*>(ebase + (size_t)kk0 * D_ + d40);
        float4 r1 = *reinterpret_cast<const float4*>(ebase + (size_t)kk1 * D_ + d41);

        __syncthreads();   // xs ready / previous kt compute done with es bufs
        // stage chunk 0 -> es0
        es0[(d40 + 0) * EPITCH + kk0] = r0.x;
        es0[(d40 + 1) * EPITCH + kk0] = r0.y;
        es0[(d40 + 2) * EPITCH + kk0] = r0.z;
        es0[(d40 + 3) * EPITCH + kk0] = r0.w;
        es0[(d41 + 0) * EPITCH + kk1] = r1.x;
        es0[(d41 + 1) * EPITCH + kk1] = r1.y;
        es0[(d41 + 2) * EPITCH + kk1] = r1.z;
        es0[(d41 + 3) * EPITCH + kk1] = r1.w;
        // prefetch chunk 1
        r0 = *reinterpret_cast<const float4*>(ebase + (size_t)kk0 * D_ + DC + d40);
        r1 = *reinterpret_cast<const float4*>(ebase + (size_t)kk1 * D_ + DC + d41);
        __syncthreads();

        for (int dc = 0; dc < D_ / DC; ++dc) {
            float* ecur = (dc & 1) ? es1 : es0;
            if (dc + 1 < D_ / DC) {
                float* enx = (dc & 1) ? es0 : es1;   // buf[(dc+1)&1]
                enx[(d40 + 0) * EPITCH + kk0] = r0.x;
                enx[(d40 + 1) * EPITCH + kk0] = r0.y;
                enx[(d40 + 2) * EPITCH + kk0] = r0.z;
                enx[(d40 + 3) * EPITCH + kk0] = r0.w;
                enx[(d41 + 0) * EPITCH + kk1] = r1.x;
                enx[(d41 + 1) * EPITCH + kk1] = r1.y;
                enx[(d41 + 2) * EPITCH + kk1] = r1.z;
                enx[(d41 + 3) * EPITCH + kk1] = r1.w;
                if (dc + 2 < D_ / DC) {
                    const float* base = ebase + (dc + 2) * DC;
                    r0 = *reinterpret_cast<const float4*>(base + (size_t)kk0 * D_ + d40);
                    r1 = *reinterpret_cast<const float4*>(base + (size_t)kk1 * D_ + d41);
                }
            }

            #pragma unroll
            for (int d = 0; d < DC; ++d) {
                const float* xr = &xs[(dc * DC + d) * BT + ty * 8];
                ulonglong2 a01 = *reinterpret_cast<const ulonglong2*>(xr);
                ulonglong2 a23 = *reinterpret_cast<const ulonglong2*>(xr + 4);
                unsigned long long a2[4] = {a01.x, a01.y, a23.x, a23.y};
                const float* er = &ecur[d * EPITCH + tx * 8];
                float4 bl = *reinterpret_cast<const float4*>(er);
                float4 bh = *reinterpret_cast<const float4*>(er + 4);
                unsigned long long bb[8];
                asm("mov.b64 %0,{%1,%1};" : "=l"(bb[0]) : "r"(__float_as_uint(bl.x)));
                asm("mov.b64 %0,{%1,%1};" : "=l"(bb[1]) : "r"(__float_as_uint(bl.y)));
                asm("mov.b64 %0,{%1,%1};" : "=l"(bb[2]) : "r"(__float_as_uint(bl.z)));
                asm("mov.b64 %0,{%1,%1};" : "=l"(bb[3]) : "r"(__float_as_uint(bl.w)));
                asm("mov.b64 %0,{%1,%1};" : "=l"(bb[4]) : "r"(__float_as_uint(bh.x)));
                asm("mov.b64 %0,{%1,%1};" : "=l"(bb[5]) : "r"(__float_as_uint(bh.y)));
                asm("mov.b64 %0,{%1,%1};" : "=l"(bb[6]) : "r"(__float_as_uint(bh.z)));
                asm("mov.b64 %0,{%1,%1};" : "=l"(bb[7]) : "r"(__float_as_uint(bh.w)));
                #pragma unroll
                for (int i2 = 0; i2 < 4; ++i2)
                    #pragma unroll
                    for (int j = 0; j < 8; ++j)
                        asm("fma.rn.f32x2 %0, %1, %2, %0;"
                            : "+l"(acc[i2][j]) : "l"(a2[i2]), "l"(bb[j]));
            }
            __syncthreads();
        }

        // write d~ tile to global
        float en[8];
        #pragma unroll
        for (int j = 0; j < 8; ++j) en[j] = __ldg(&g_B[kb + tx * 8 + j]);
        #pragma unroll
        for (int i2 = 0; i2 < 4; ++i2) {
            float v0[8], v1[8];
            #pragma unroll
            for (int j = 0; j < 8; ++j) {
                unsigned long long v = acc[i2][j];
                v0[j] = fmaf(-2.0f, __uint_as_float((unsigned)v), en[j]);
                v1[j] = fmaf(-2.0f, __uint_as_float((unsigned)(v >> 32)), en[j]);
            }
            int t0 = n0 + ty * 8 + 2 * i2;
            float* p0 = g_dist + (size_t)t0 * K_ + kb + tx * 8;
            *reinterpret_cast<float4*>(p0)     = make_float4(v0[0], v0[1], v0[2], v0[3]);
            *reinterpret_cast<float4*>(p0 + 4) = make_float4(v0[4], v0[5], v0[6], v0[7]);
            float* p1 = p0 + K_;
            *reinterpret_cast<float4*>(p1)     = make_float4(v1[0], v1[1], v1[2], v1[3]);
            *reinterpret_cast<float4*>(p1 + 4) = make_float4(v1[4], v1[5], v1[6], v1[7]);
        }
    }
}

// ---------------------------------------------------------
__device__ __forceinline__ unsigned order_f(float f) {
    unsigned u = __float_as_uint(f);
    return (u & 0x80000000u) ? ~u : (u | 0x80000000u);
}

// Phase 2 v2: streaming top-2 min; fp64 ulp-bucket emulation only when
// second-min is within EPSM of min (incl. all exact ties).
__global__ void __launch_bounds__(256)
select_kernel(const float* __restrict__ IN, const float* __restrict__ E) {
    const int warp = threadIdx.x >> 5;
    const int lane = threadIdx.x & 31;
    const int n = blockIdx.x * 8 + warp;

    const float4* dr4 = reinterpret_cast<const float4*>(g_dist + (size_t)n * K_);

    float m1 = 3.4e38f, m2 = 3.4e38f;
    int ki = 0;
    #pragma unroll
    for (int j = 0; j < 8; ++j) {
        float4 v = dr4[lane + 32 * j];
        int kb = 4 * (lane + 32 * j);
        if (v.x < m1) { m2 = m1; m1 = v.x; ki = kb;     } else if (v.x < m2) m2 = v.x;
        if (v.y < m1) { m2 = m1; m1 = v.y; ki = kb + 1; } else if (v.y < m2) m2 = v.y;
        if (v.z < m1) { m2 = m1; m1 = v.z; ki = kb + 2; } else if (v.z < m2) m2 = v.z;
        if (v.w < m1) { m2 = m1; m1 = v.w; ki = kb + 3; } else if (v.w < m2) m2 = v.w;
    }
    // warp merge of (m1, m2, ki); exact cross-lane ties collapse m2 -> m1 (rare path)
    #pragma unroll
    for (int off = 16; off > 0; off >>= 1) {
        float o1 = __shfl_xor_sync(0xFFFFFFFFu, m1, off);
        float o2 = __shfl_xor_sync(0xFFFFFFFFu, m2, off);
        int   oi = __shfl_xor_sync(0xFFFFFFFFu, ki, off);
        float hi  = fmaxf(m1, o1);
        float nm2 = fminf(hi, fminf(m2, o2));
        if (o1 < m1 || (o1 == m1 && oi < ki)) ki = oi;
        m1 = fminf(m1, o1);
        m2 = nm2;
    }
    const float thresh = m1 + EPSM;

    int k_final = ki;
    if (m2 <= thresh) {
        // rare path: exact emulation of reference fp32 rounding
        const int b = n >> 10, hw = n & (HW_ - 1);
        const float* xb = IN + (size_t)b * (D_ * HW_) + hw;

        double a = 0.0;
        #pragma unroll
        for (int d = lane; d < D_; d += 32) {
            double x = (double)xb[(size_t)d * HW_];
            a += x * x;
        }
        #pragma unroll
        for (int off = 16; off > 0; off >>= 1)
            a += __shfl_xor_sync(0xFFFFFFFFu, a, off);
        float Af = (float)a;

        unsigned long long key = 0xFFFFFFFFFFFFFFFFull;
        #pragma unroll
        for (int j = 0; j < 8; ++j) {
            float4 v = dr4[lane + 32 * j];
            float vv[4] = {v.x, v.y, v.z, v.w};
            #pragma unroll
            for (int c = 0; c < 4; ++c) {
                if (vv[c] <= thresh) {
                    int k = 4 * (lane + 32 * j) + c;
                    const float* er = E + (size_t)k * D_;
                    double dot = 0.0;
                    for (int d = 0; d < D_; ++d)
                        dot += (double)xb[(size_t)d * HW_] * (double)er[d];
                    float Mf = (float)dot;
                    float T  = Af + __ldg(&g_B[k]);   // fl32
                    float ds = T - 2.0f * Mf;         // fl32
                    unsigned long long kk =
                        ((unsigned long long)order_f(ds) << 32) | (unsigned)k;
                    if (kk < key) key = kk;
                }
            }
        }
        #pragma unroll
        for (int off = 16; off > 0; off >>= 1) {
            unsigned long long o = __shfl_xor_sync(0xFFFFFFFFu, key, off);
            if (o < key) key = o;
        }
        k_final = (int)(unsigned)key;
    }

    if (lane == 0) {
        g_idx[n] = k_final;
        atomicAdd(&g_counts[k_final], 1);
    }
}

// ---------------------------------------------------------
__global__ void __launch_bounds__(256, 1)
gather_kernel(const float* __restrict__ IN, const float* __restrict__ E,
              float* __restrict__ OUT) {
    extern __shared__ float smem[];
    float* qs   = smem;                          // [128][257]
    int*   sidx = (int*)(smem + 128 * 257);
    float* red  = smem + 128 * 257 + 128;

    const int tid = threadIdx.x;
    const int n0  = blockIdx.x * BT;

    if (tid < BT) sidx[tid] = g_idx[n0 + tid];
    __syncthreads();

    #pragma unroll 4
    for (int it = 0; it < BT; ++it)
        qs[it * 257 + tid] = E[(size_t)sidx[it] * D_ + tid];
    __syncthreads();

    const int b = n0 >> 10, hw0 = n0 & (HW_ - 1);
    const size_t base = (size_t)b * (D_ * HW_) + hw0;
    float lsum = 0.0f;
    #pragma unroll 4
    for (int it = 0; it < 128; ++it) {
        int j = it * 256 + tid;
        int d = j >> 7;
        int t = j & 127;
        size_t a = base + (size_t)d * HW_ + t;
        float x = IN[a];
        float q = qs[t * 257 + d];
        OUT[a] = q;
        float df = q - x;
        lsum += df * df;
    }
    red[tid] = lsum;
    __syncthreads();
    for (int s = 128; s > 0; s >>= 1) {
        if (tid < s) red[tid] += red[tid + s];
        __syncthreads();
    }
    if (tid == 0) g_partials[blockIdx.x] = red[0];
}

// ---------------------------------------------------------
__global__ void finalize_kernel(float* __restrict__ OUT, int out_size) {
    __shared__ float red[256];
    int tid = threadIdx.x;

    red[tid] = g_partials[tid];
    __syncthreads();
    for (int s = 128; s > 0; s >>= 1) {
        if (tid < s) red[tid] += red[tid + s];
        __syncthreads();
    }
    float loss = 1.25f * red[0] / (float)NELEM_;
    __syncthreads();

    float ps = 0.0f;
    for (int i = tid; i < K_; i += 256) {
        float p = (float)g_counts[i] / (float)N_;
        ps += p * logf(p + 1e-10f);
    }
    red[tid] = ps;
    __syncthreads();
    for (int s = 128; s > 0; s >>= 1) {
        if (tid < s) red[tid] += red[tid + s];
        __syncthreads();
    }
    if (tid == 0) {
        float perp = expf(-red[0]);
        if (out_size > NELEM_)     OUT[NELEM_]     = loss;
        if (out_size > NELEM_ + 1) OUT[NELEM_ + 1] = perp;
    }
}

// ---------------------------------------------------------
extern "C" void kernel_launch(void* const* d_in, const int* in_sizes, int n_in,
                              void* d_out, int out_size) {
    const float* IN = (const float*)d_in[0];
    const float* E  = (const float*)d_in[1];
    float* OUT = (float*)d_out;

    const int smemB = (D_ * BT + 2 * DC * EPITCH) * (int)sizeof(float);
    const int smemC = (128 * 257 + 128 + 256) * (int)sizeof(float);
    cudaFuncSetAttribute(dist_kernel,   cudaFuncAttributeMaxDynamicSharedMemorySize, smemB);
    cudaFuncSetAttribute(gather_kernel, cudaFuncAttributeMaxDynamicSharedMemorySize, smemC);

    init_kernel<<<4, 256>>>();
    enorm_kernel<<<K_, 256>>>(E);
    dist_kernel<<<dim3(N_ / BT, K_ / BK), 256, smemB>>>(IN, E);
    select_kernel<<<N_ / 8, 256>>>(IN, E);
    gather_kernel<<<N_ / BT, 256, smemC>>>(IN, E, OUT);
    finalize_kernel<<<1, 256>>>(OUT, out_size);
}

// round 5
// speedup vs baseline: 1.7074x; 1.6191x over previous
#include <cuda_runtime.h>
#include <math.h>

#define D_    256
#define HW_   1024
#define N_    32768
#define K_    1024
#define NELEM_ 8388608

#define BT2   64                // tokens per dist block
#define BKK   256               // codes per dist block
#define DC    16
#define EPITCH2 260
#define BT    128               // gather tile
#define EPSM  3e-4f

// -------- device scratch --------
__device__ float g_dist[N_ * (size_t)K_];   // 128 MiB approx distances (minus ||x||^2)
__device__ float g_B[K_];                   // fl32(f64 sum e^2)
__device__ int   g_idx[N_];
__device__ int   g_counts[K_];
__device__ float g_partials[N_ / BT];

// ---------------------------------------------------------
__global__ void init_kernel() {
    int i = blockIdx.x * blockDim.x + threadIdx.x;
    if (i < K_) g_counts[i] = 0;
}

__global__ void enorm_kernel(const float* __restrict__ E) {
    __shared__ double red[256];
    int k = blockIdx.x;
    float v = E[(size_t)k * D_ + threadIdx.x];
    red[threadIdx.x] = (double)v * (double)v;
    __syncthreads();
    for (int s = 128; s > 0; s >>= 1) {
        if (threadIdx.x < s) red[threadIdx.x] += red[threadIdx.x + s];
        __syncthreads();
    }
    if (threadIdx.x == 0) g_B[k] = (float)red[0];
}

// ---------------------------------------------------------
// Phase 1: d~ = ||e||^2 - 2 x.e  (fp32, f32x2 FMA)
// 64 tokens x 256 codes per block, 256 threads, 2 blocks/SM.
__global__ void __launch_bounds__(256, 2)
dist_kernel(const float* __restrict__ IN, const float* __restrict__ E) {
    extern __shared__ float smem[];
    float* xs  = smem;                        // [256 d][64 t] = 64 KB
    float* es0 = smem + D_ * BT2;             // [DC][EPITCH2]
    float* es1 = es0 + DC * EPITCH2;

    const int tid = threadIdx.x;
    const int tx  = tid & 31;                 // 32 code groups x 8 = 256 codes
    const int ty  = tid >> 5;                 // 8 token groups x 8 = 64 tokens

    const int n0  = blockIdx.x * BT2;
    const int b   = n0 >> 10;
    const int hw0 = n0 & (HW_ - 1);
    const float* inb = IN + (size_t)b * (D_ * HW_) + hw0;

    // xs load: [d][t], coalesced float4 along tokens
    #pragma unroll
    for (int it = 0; it < 16; ++it) {
        int j  = it * 256 + tid;              // 4096 float4
        int t4 = j & 15;
        int d  = j >> 4;
        float4 v = *reinterpret_cast<const float4*>(inb + (size_t)d * HW_ + t4 * 4);
        *reinterpret_cast<float4*>(&xs[d * BT2 + t4 * 4]) = v;
    }

    const int kb = blockIdx.y * BKK;
    const float* ebase = E + (size_t)kb * D_;

    unsigned long long acc[4][8];
    #pragma unroll
    for (int i = 0; i < 4; ++i)
        #pragma unroll
        for (int j = 0; j < 8; ++j) acc[i][j] = 0ull;

    // e-chunk loader mapping: f = tid + 256p, k = f>>2, d4 = (f&3)*4
    float4 r[4];
    #pragma unroll
    for (int p = 0; p < 4; ++p) {
        int f = tid + 256 * p;
        r[p] = *reinterpret_cast<const float4*>(ebase + (size_t)(f >> 2) * D_ + (f & 3) * 4);
    }

    __syncthreads();                          // xs visible
    // stage chunk 0 -> es0
    #pragma unroll
    for (int p = 0; p < 4; ++p) {
        int f = tid + 256 * p;
        int k = f >> 2, d4 = (f & 3) * 4;
        es0[(d4 + 0) * EPITCH2 + k] = r[p].x;
        es0[(d4 + 1) * EPITCH2 + k] = r[p].y;
        es0[(d4 + 2) * EPITCH2 + k] = r[p].z;
        es0[(d4 + 3) * EPITCH2 + k] = r[p].w;
    }
    // prefetch chunk 1
    #pragma unroll
    for (int p = 0; p < 4; ++p) {
        int f = tid + 256 * p;
        r[p] = *reinterpret_cast<const float4*>(ebase + (size_t)(f >> 2) * D_ + DC + (f & 3) * 4);
    }
    __syncthreads();

    for (int dc = 0; dc < D_ / DC; ++dc) {
        float* ecur = (dc & 1) ? es1 : es0;
        if (dc + 1 < D_ / DC) {
            float* enx = (dc & 1) ? es0 : es1;
            #pragma unroll
            for (int p = 0; p < 4; ++p) {
                int f = tid + 256 * p;
                int k = f >> 2, d4 = (f & 3) * 4;
                enx[(d4 + 0) * EPITCH2 + k] = r[p].x;
                enx[(d4 + 1) * EPITCH2 + k] = r[p].y;
                enx[(d4 + 2) * EPITCH2 + k] = r[p].z;
                enx[(d4 + 3) * EPITCH2 + k] = r[p].w;
            }
            if (dc + 2 < D_ / DC) {
                const float* base = ebase + (dc + 2) * DC;
                #pragma unroll
                for (int p = 0; p < 4; ++p) {
                    int f = tid + 256 * p;
                    r[p] = *reinterpret_cast<const float4*>(base + (size_t)(f >> 2) * D_ + (f & 3) * 4);
                }
            }
        }

        #pragma unroll
        for (int d = 0; d < DC; ++d) {
            const float* xr = &xs[(dc * DC + d) * BT2 + ty * 8];
            ulonglong2 a01 = *reinterpret_cast<const ulonglong2*>(xr);
            ulonglong2 a23 = *reinterpret_cast<const ulonglong2*>(xr + 4);
            unsigned long long a2[4] = {a01.x, a01.y, a23.x, a23.y};
            const float* er = &ecur[d * EPITCH2 + tx * 8];
            float4 bl = *reinterpret_cast<const float4*>(er);
            float4 bh = *reinterpret_cast<const float4*>(er + 4);
            unsigned long long bb[8];
            asm("mov.b64 %0,{%1,%1};" : "=l"(bb[0]) : "r"(__float_as_uint(bl.x)));
            asm("mov.b64 %0,{%1,%1};" : "=l"(bb[1]) : "r"(__float_as_uint(bl.y)));
            asm("mov.b64 %0,{%1,%1};" : "=l"(bb[2]) : "r"(__float_as_uint(bl.z)));
            asm("mov.b64 %0,{%1,%1};" : "=l"(bb[3]) : "r"(__float_as_uint(bl.w)));
            asm("mov.b64 %0,{%1,%1};" : "=l"(bb[4]) : "r"(__float_as_uint(bh.x)));
            asm("mov.b64 %0,{%1,%1};" : "=l"(bb[5]) : "r"(__float_as_uint(bh.y)));
            asm("mov.b64 %0,{%1,%1};" : "=l"(bb[6]) : "r"(__float_as_uint(bh.z)));
            asm("mov.b64 %0,{%1,%1};" : "=l"(bb[7]) : "r"(__float_as_uint(bh.w)));
            #pragma unroll
            for (int i2 = 0; i2 < 4; ++i2)
                #pragma unroll
                for (int j = 0; j < 8; ++j)
                    asm("fma.rn.f32x2 %0, %1, %2, %0;"
                        : "+l"(acc[i2][j]) : "l"(a2[i2]), "l"(bb[j]));
        }
        __syncthreads();
    }

    // epilogue: d~ = ||e||^2 - 2*dot
    float en[8];
    #pragma unroll
    for (int j = 0; j < 8; ++j) en[j] = __ldg(&g_B[kb + tx * 8 + j]);
    #pragma unroll
    for (int i2 = 0; i2 < 4; ++i2) {
        float v0[8], v1[8];
        #pragma unroll
        for (int j = 0; j < 8; ++j) {
            unsigned long long v = acc[i2][j];
            v0[j] = fmaf(-2.0f, __uint_as_float((unsigned)v), en[j]);
            v1[j] = fmaf(-2.0f, __uint_as_float((unsigned)(v >> 32)), en[j]);
        }
        int t0 = n0 + ty * 8 + 2 * i2;
        float* p0 = g_dist + (size_t)t0 * K_ + kb + tx * 8;
        *reinterpret_cast<float4*>(p0)     = make_float4(v0[0], v0[1], v0[2], v0[3]);
        *reinterpret_cast<float4*>(p0 + 4) = make_float4(v0[4], v0[5], v0[6], v0[7]);
        float* p1 = p0 + K_;
        *reinterpret_cast<float4*>(p1)     = make_float4(v1[0], v1[1], v1[2], v1[3]);
        *reinterpret_cast<float4*>(p1 + 4) = make_float4(v1[4], v1[5], v1[6], v1[7]);
    }
}

// ---------------------------------------------------------
__device__ __forceinline__ unsigned order_f(float f) {
    unsigned u = __float_as_uint(f);
    return (u & 0x80000000u) ? ~u : (u | 0x80000000u);
}

// Phase 2 v3: batched loads (MLP=8) + warp-cooperative rare path.
__global__ void __launch_bounds__(256)
select_kernel(const float* __restrict__ IN, const float* __restrict__ E) {
    const int warp = threadIdx.x >> 5;
    const int lane = threadIdx.x & 31;
    const int n = blockIdx.x * 8 + warp;

    const float4* dr4 = reinterpret_cast<const float4*>(g_dist + (size_t)n * K_);

    float4 v[8];
    #pragma unroll
    for (int j = 0; j < 8; ++j) v[j] = dr4[lane + 32 * j];   // 8 independent LDG.128

    float m1 = 3.4e38f, m2 = 3.4e38f;
    int ki = 0;
    #pragma unroll
    for (int j = 0; j < 8; ++j) {
        float vv[4] = {v[j].x, v[j].y, v[j].z, v[j].w};
        int kb = 4 * (lane + 32 * j);
        #pragma unroll
        for (int c = 0; c < 4; ++c) {
            if (vv[c] < m1) { m2 = m1; m1 = vv[c]; ki = kb + c; }
            else if (vv[c] < m2) m2 = vv[c];
        }
    }
    #pragma unroll
    for (int off = 16; off > 0; off >>= 1) {
        float o1 = __shfl_xor_sync(0xFFFFFFFFu, m1, off);
        float o2 = __shfl_xor_sync(0xFFFFFFFFu, m2, off);
        int   oi = __shfl_xor_sync(0xFFFFFFFFu, ki, off);
        float hi  = fmaxf(m1, o1);
        float nm2 = fminf(hi, fminf(m2, o2));
        if (o1 < m1 || (o1 == m1 && oi < ki)) ki = oi;
        m1 = fminf(m1, o1);
        m2 = nm2;
    }
    const float thresh = m1 + EPSM;

    int k_final = ki;
    if (m2 <= thresh) {
        // rare path (~5% tokens): warp-cooperative exact fp32-rounding emulation
        const int b = n >> 10, hw = n & (HW_ - 1);
        const float* xb = IN + (size_t)b * (D_ * HW_) + hw;

        float xr[8];
        #pragma unroll
        for (int t = 0; t < 8; ++t)
            xr[t] = xb[(size_t)(lane + 32 * t) * HW_];

        double a = 0.0;
        #pragma unroll
        for (int t = 0; t < 8; ++t) a += (double)xr[t] * (double)xr[t];
        #pragma unroll
        for (int off = 16; off > 0; off >>= 1)
            a += __shfl_xor_sync(0xFFFFFFFFu, a, off);
        float Af = (float)a;

        unsigned cmask = 0;                // bit (4j+c): candidate among my 32 codes
        #pragma unroll
        for (int j = 0; j < 8; ++j) {
            float vv[4] = {v[j].x, v[j].y, v[j].z, v[j].w};
            #pragma unroll
            for (int c = 0; c < 4; ++c)
                if (vv[c] <= thresh) cmask |= 1u << (4 * j + c);
        }

        unsigned long long key = 0xFFFFFFFFFFFFFFFFull;
        while (true) {
            unsigned ball = __ballot_sync(0xFFFFFFFFu, cmask != 0);
            if (!ball) break;
            int leader = __ffs(ball) - 1;
            unsigned lm = __shfl_sync(0xFFFFFFFFu, cmask, leader);
            int bit = __ffs(lm) - 1;
            int k = 4 * (leader + 32 * (bit >> 2)) + (bit & 3);
            if (lane == leader) cmask &= cmask - 1;

            const float* er = E + (size_t)k * D_;
            double dot = 0.0;
            #pragma unroll
            for (int t = 0; t < 8; ++t)
                dot += (double)xr[t] * (double)er[lane + 32 * t];
            #pragma unroll
            for (int off = 16; off > 0; off >>= 1)
                dot += __shfl_xor_sync(0xFFFFFFFFu, dot, off);

            float Mf = (float)dot;
            float T  = Af + __ldg(&g_B[k]);   // fl32
            float ds = T - 2.0f * Mf;         // fl32
            unsigned long long kk =
                ((unsigned long long)order_f(ds) << 32) | (unsigned)k;
            if (kk < key) key = kk;           // identical on all lanes
        }
        k_final = (int)(unsigned)key;
    }

    if (lane == 0) {
        g_idx[n] = k_final;
        atomicAdd(&g_counts[k_final], 1);
    }
}

// ---------------------------------------------------------
__global__ void __launch_bounds__(256, 1)
gather_kernel(const float* __restrict__ IN, const float* __restrict__ E,
              float* __restrict__ OUT) {
    extern __shared__ float smem[];
    float* qs   = smem;                          // [128][257]
    int*   sidx = (int*)(smem + 128 * 257);
    float* red  = smem + 128 * 257 + 128;

    const int tid = threadIdx.x;
    const int n0  = blockIdx.x * BT;

    if (tid < BT) sidx[tid] = g_idx[n0 + tid];
    __syncthreads();

    #pragma unroll 4
    for (int it = 0; it < BT; ++it)
        qs[it * 257 + tid] = E[(size_t)sidx[it] * D_ + tid];
    __syncthreads();

    const int b = n0 >> 10, hw0 = n0 & (HW_ - 1);
    const size_t base = (size_t)b * (D_ * HW_) + hw0;
    float lsum = 0.0f;
    #pragma unroll 4
    for (int it = 0; it < 128; ++it) {
        int j = it * 256 + tid;
        int d = j >> 7;
        int t = j & 127;
        size_t a = base + (size_t)d * HW_ + t;
        float x = IN[a];
        float q = qs[t * 257 + d];
        OUT[a] = q;
        float df = q - x;
        lsum += df * df;
    }
    red[tid] = lsum;
    __syncthreads();
    for (int s = 128; s > 0; s >>= 1) {
        if (tid < s) red[tid] += red[tid + s];
        __syncthreads();
    }
    if (tid == 0) g_partials[blockIdx.x] = red[0];
}

// ---------------------------------------------------------
__global__ void finalize_kernel(float* __restrict__ OUT, int out_size) {
    __shared__ float red[256];
    int tid = threadIdx.x;

    red[tid] = g_partials[tid];
    __syncthreads();
    for (int s = 128; s > 0; s >>= 1) {
        if (tid < s) red[tid] += red[tid + s];
        __syncthreads();
    }
    float loss = 1.25f * red[0] / (float)NELEM_;
    __syncthreads();

    float ps = 0.0f;
    for (int i = tid; i < K_; i += 256) {
        float p = (float)g_counts[i] / (float)N_;
        ps += p * logf(p + 1e-10f);
    }
    red[tid] = ps;
    __syncthreads();
    for (int s = 128; s > 0; s >>= 1) {
        if (tid < s) red[tid] += red[tid + s];
        __syncthreads();
    }
    if (tid == 0) {
        float perp = expf(-red[0]);
        if (out_size > NELEM_)     OUT[NELEM_]     = loss;
        if (out_size > NELEM_ + 1) OUT[NELEM_ + 1] = perp;
    }
}

// ---------------------------------------------------------
extern "C" void kernel_launch(void* const* d_in, const int* in_sizes, int n_in,
                              void* d_out, int out_size) {
    const float* IN = (const float*)d_in[0];
    const float* E  = (const float*)d_in[1];
    float* OUT = (float*)d_out;

    const int smemB = (D_ * BT2 + 2 * DC * EPITCH2) * (int)sizeof(float);  // 98,816 B
    const int smemC = (128 * 257 + 128 + 256) * (int)sizeof(float);
    cudaFuncSetAttribute(dist_kernel,   cudaFuncAttributeMaxDynamicSharedMemorySize, smemB);
    cudaFuncSetAttribute(gather_kernel, cudaFuncAttributeMaxDynamicSharedMemorySize, smemC);

    init_kernel<<<4, 256>>>();
    enorm_kernel<<<K_, 256>>>(E);
    dist_kernel<<<dim3(N_ / BT2, K_ / BKK), 256, smemB>>>(IN, E);
    select_kernel<<<N_ / 8, 256>>>(IN, E);
    gather_kernel<<<N_ / BT, 256, smemC>>>(IN, E, OUT);
    finalize_kernel<<<1, 256>>>(OUT, out_size);
}

// round 8
// speedup vs baseline: 3.9120x; 2.2912x over previous
#include <cuda_runtime.h>
#include <cuda_bf16.h>
#include <cstdint>
#include <math.h>

#define D_    256
#define HW_   1024
#define N_    32768
#define K_    1024
#define NELEM_ 8388608
#define BT    128
#define EPSM  1e-3f

#define APITCH 264              // padded bf16 row stride for smem tiles

// -------- device scratch --------
__device__ float          g_dist[N_ * (size_t)K_];  // 128 MiB
__device__ float          g_B[K_];                  // fl32(f64 sum e^2)
__device__ int            g_idx[N_];
__device__ int            g_counts[K_];
__device__ float          g_partials[N_ / BT];
__device__ unsigned short g_Xb[N_ * D_];            // bf16 X, token-major
__device__ unsigned short g_Eb[K_ * D_];            // bf16 E, code-major

// -------- helpers --------
__device__ __forceinline__ unsigned short f2bf(float x) {
    __nv_bfloat16 b = __float2bfloat16(x);
    return *reinterpret_cast<unsigned short*>(&b);
}
__device__ __forceinline__ uint32_t smem_u32(const void* p) {
    uint32_t a;
    asm("{ .reg .u64 t; cvta.to.shared.u64 t, %1; cvt.u32.u64 %0, t; }" : "=r"(a) : "l"(p));
    return a;
}
__device__ __forceinline__ void ldsm_x4(uint32_t& r0, uint32_t& r1,
                                        uint32_t& r2, uint32_t& r3, uint32_t addr) {
    asm volatile("ldmatrix.sync.aligned.m8n8.x4.shared.b16 {%0,%1,%2,%3}, [%4];"
                 : "=r"(r0), "=r"(r1), "=r"(r2), "=r"(r3) : "r"(addr));
}
__device__ __forceinline__ void mma16816(float& c0, float& c1, float& c2, float& c3,
                                         uint32_t a0, uint32_t a1, uint32_t a2, uint32_t a3,
                                         uint32_t b0, uint32_t b1) {
    asm volatile(
        "mma.sync.aligned.m16n8k16.row.col.f32.bf16.bf16.f32 "
        "{%0,%1,%2,%3}, {%4,%5,%6,%7}, {%8,%9}, {%0,%1,%2,%3};"
        : "+f"(c0), "+f"(c1), "+f"(c2), "+f"(c3)
        : "r"(a0), "r"(a1), "r"(a2), "r"(a3), "r"(b0), "r"(b1));
}

// ---------------------------------------------------------
__global__ void init_kernel() {
    int i = blockIdx.x * blockDim.x + threadIdx.x;
    if (i < K_) g_counts[i] = 0;
}

__global__ void enorm_kernel(const float* __restrict__ E) {
    __shared__ double red[256];
    int k = blockIdx.x;
    float v = E[(size_t)k * D_ + threadIdx.x];
    red[threadIdx.x] = (double)v * (double)v;
    __syncthreads();
    for (int s = 128; s > 0; s >>= 1) {
        if (threadIdx.x < s) red[threadIdx.x] += red[threadIdx.x + s];
        __syncthreads();
    }
    if (threadIdx.x == 0) g_B[k] = (float)red[0];
}

__global__ void ebf_kernel(const float* __restrict__ E) {
    int k = blockIdx.x;
    g_Eb[k * D_ + threadIdx.x] = f2bf(E[(size_t)k * D_ + threadIdx.x]);
}

// ---------------------------------------------------------
// X convert + transpose: [d][token] fp32 -> token-major bf16 rows.
__global__ void __launch_bounds__(256, 1)
xbf_kernel(const float* __restrict__ IN) {
    extern __shared__ unsigned short sm[];   // [256 d][128 t]

    const int tid = threadIdx.x;
    const int n0  = blockIdx.x * BT;
    const int b   = n0 >> 10;
    const int hw0 = n0 & (HW_ - 1);
    const float* inb = IN + (size_t)b * (D_ * HW_) + hw0;

    #pragma unroll
    for (int it = 0; it < 32; ++it) {
        int j  = it * 256 + tid;
        int t4 = j & 31;
        int d  = j >> 5;
        float4 v = *reinterpret_cast<const float4*>(inb + (size_t)d * HW_ + t4 * 4);
        uint32_t* p = reinterpret_cast<uint32_t*>(&sm[d * BT + t4 * 4]);
        p[0] = (uint32_t)f2bf(v.x) | ((uint32_t)f2bf(v.y) << 16);
        p[1] = (uint32_t)f2bf(v.z) | ((uint32_t)f2bf(v.w) << 16);
    }
    __syncthreads();

    // transpose out: thread -> token t = tid&127, half = tid>>7
    const int t    = tid & 127;
    const int half = tid >> 7;
    #pragma unroll
    for (int c = 0; c < 16; ++c) {
        int d0 = half * 128 + c * 8;
        unsigned short u[8];
        #pragma unroll
        for (int i = 0; i < 8; ++i) u[i] = sm[(d0 + i) * BT + t];
        uint4 q;
        q.x = (uint32_t)u[0] | ((uint32_t)u[1] << 16);
        q.y = (uint32_t)u[2] | ((uint32_t)u[3] << 16);
        q.z = (uint32_t)u[4] | ((uint32_t)u[5] << 16);
        q.w = (uint32_t)u[6] | ((uint32_t)u[7] << 16);
        *reinterpret_cast<uint4*>(&g_Xb[(size_t)(n0 + t) * D_ + d0]) = q;
    }
}

// ---------------------------------------------------------
// HMMA distance GEMM: block = 128 tokens x 128 codes, K=256 resident.
// d~ = ||e||^2 - 2 * x.e  written to g_dist.
#define SMEM_MMA (2 * BT * APITCH * 2)     // A + B tiles, bf16

__global__ void __launch_bounds__(256, 1)
dist_mma_kernel() {
    extern __shared__ unsigned short sAB[];
    unsigned short* As = sAB;                    // [128 tok][264]
    unsigned short* Bs = sAB + BT * APITCH;      // [128 code][264]

    const int tid  = threadIdx.x;
    const int wid  = tid >> 5;
    const int lane = tid & 31;
    const int wm   = wid & 3;        // 4 M-groups x 32 tokens
    const int wn   = wid >> 2;       // 2 N-groups x 64 codes
    const int n0   = blockIdx.x * BT;
    const int kq   = blockIdx.y;     // 8 code quadrants of 128

    // load tiles (16 uint4 per thread each)
    #pragma unroll
    for (int it = 0; it < 16; ++it) {
        int idx = it * 256 + tid;
        int row = idx >> 5, c = idx & 31;
        *reinterpret_cast<uint4*>(&As[row * APITCH + c * 8]) =
            *reinterpret_cast<const uint4*>(&g_Xb[(size_t)(n0 + row) * D_ + c * 8]);
        *reinterpret_cast<uint4*>(&Bs[row * APITCH + c * 8]) =
            *reinterpret_cast<const uint4*>(&g_Eb[(size_t)(kq * BT + row) * D_ + c * 8]);
    }
    __syncthreads();

    const uint32_t aBase = smem_u32(As);
    const uint32_t bBase = smem_u32(Bs);

    float acc[2][8][4];
    #pragma unroll
    for (int i = 0; i < 2; ++i)
        #pragma unroll
        for (int j = 0; j < 8; ++j)
            #pragma unroll
            for (int c = 0; c < 4; ++c) acc[i][j][c] = 0.0f;

    // A ldmatrix address: row = wm*32 + msub*16 + lane%16, col byte = k*2 + (lane/16)*16
    const int aRow = wm * 32 + (lane & 15);
    const uint32_t aOff = aBase + (uint32_t)aRow * (APITCH * 2) + (uint32_t)(lane >> 4) * 16;
    // B ldmatrix address: row = wn*64 + ng*16 + (lane&7) + (lane>=16)*8, col = k*2 + ((lane>>3)&1)*16
    const int bRow = wn * 64 + (lane & 7) + ((lane >> 4) << 3);
    const uint32_t bOff = bBase + (uint32_t)bRow * (APITCH * 2) + (uint32_t)((lane >> 3) & 1) * 16;

    #pragma unroll
    for (int ks = 0; ks < D_ / 16; ++ks) {
        const uint32_t kb = ks * 32;     // bytes
        uint32_t a[2][4];
        ldsm_x4(a[0][0], a[0][1], a[0][2], a[0][3], aOff + kb);
        ldsm_x4(a[1][0], a[1][1], a[1][2], a[1][3], aOff + 16 * (APITCH * 2) + kb);
        uint32_t bfr[8][2];
        #pragma unroll
        for (int ng = 0; ng < 4; ++ng) {
            uint32_t r0, r1, r2, r3;
            ldsm_x4(r0, r1, r2, r3, bOff + (uint32_t)ng * 16 * (APITCH * 2) + kb);
            bfr[2 * ng][0] = r0; bfr[2 * ng][1] = r1;
            bfr[2 * ng + 1][0] = r2; bfr[2 * ng + 1][1] = r3;
        }
        #pragma unroll
        for (int msub = 0; msub < 2; ++msub)
            #pragma unroll
            for (int nn = 0; nn < 8; ++nn)
                mma16816(acc[msub][nn][0], acc[msub][nn][1],
                         acc[msub][nn][2], acc[msub][nn][3],
                         a[msub][0], a[msub][1], a[msub][2], a[msub][3],
                         bfr[nn][0], bfr[nn][1]);
    }

    // epilogue: d~ = en - 2*dot ; C frag: rows l/4, l/4+8; cols 2(l%4), +1
    #pragma unroll
    for (int msub = 0; msub < 2; ++msub) {
        int tok = n0 + wm * 32 + msub * 16 + (lane >> 2);
        #pragma unroll
        for (int nn = 0; nn < 8; ++nn) {
            int code = kq * BT + wn * 64 + nn * 8 + 2 * (lane & 3);
            float2 en = *reinterpret_cast<const float2*>(&g_B[code]);
            float2 lo, hi;
            lo.x = fmaf(-2.0f, acc[msub][nn][0], en.x);
            lo.y = fmaf(-2.0f, acc[msub][nn][1], en.y);
            hi.x = fmaf(-2.0f, acc[msub][nn][2], en.x);
            hi.y = fmaf(-2.0f, acc[msub][nn][3], en.y);
            *reinterpret_cast<float2*>(&g_dist[(size_t)tok * K_ + code]) = lo;
            *reinterpret_cast<float2*>(&g_dist[(size_t)(tok + 8) * K_ + code]) = hi;
        }
    }
}

// ---------------------------------------------------------
__device__ __forceinline__ unsigned order_f(float f) {
    unsigned u = __float_as_uint(f);
    return (u & 0x80000000u) ? ~u : (u | 0x80000000u);
}

// Streaming top-2 min; fp64 exact-fp32-emulation path when within EPSM.
__global__ void __launch_bounds__(256)
select_kernel(const float* __restrict__ IN, const float* __restrict__ E) {
    const int warp = threadIdx.x >> 5;
    const int lane = threadIdx.x & 31;
    const int n = blockIdx.x * 8 + warp;

    const float4* dr4 = reinterpret_cast<const float4*>(g_dist + (size_t)n * K_);

    float4 v[8];
    #pragma unroll
    for (int j = 0; j < 8; ++j) v[j] = dr4[lane + 32 * j];

    float m1 = 3.4e38f, m2 = 3.4e38f;
    int ki = 0;
    #pragma unroll
    for (int j = 0; j < 8; ++j) {
        float vv[4] = {v[j].x, v[j].y, v[j].z, v[j].w};
        int kb = 4 * (lane + 32 * j);
        #pragma unroll
        for (int c = 0; c < 4; ++c) {
            if (vv[c] < m1) { m2 = m1; m1 = vv[c]; ki = kb + c; }
            else if (vv[c] < m2) m2 = vv[c];
        }
    }
    #pragma unroll
    for (int off = 16; off > 0; off >>= 1) {
        float o1 = __shfl_xor_sync(0xFFFFFFFFu, m1, off);
        float o2 = __shfl_xor_sync(0xFFFFFFFFu, m2, off);
        int   oi = __shfl_xor_sync(0xFFFFFFFFu, ki, off);
        float hi  = fmaxf(m1, o1);
        float nm2 = fminf(hi, fminf(m2, o2));
        if (o1 < m1 || (o1 == m1 && oi < ki)) ki = oi;
        m1 = fminf(m1, o1);
        m2 = nm2;
    }
    const float thresh = m1 + EPSM;

    int k_final = ki;
    if (m2 <= thresh) {
        const int b = n >> 10, hw = n & (HW_ - 1);
        const float* xb = IN + (size_t)b * (D_ * HW_) + hw;

        float xr[8];
        #pragma unroll
        for (int t = 0; t < 8; ++t)
            xr[t] = xb[(size_t)(lane + 32 * t) * HW_];

        double a = 0.0;
        #pragma unroll
        for (int t = 0; t < 8; ++t) a += (double)xr[t] * (double)xr[t];
        #pragma unroll
        for (int off = 16; off > 0; off >>= 1)
            a += __shfl_xor_sync(0xFFFFFFFFu, a, off);
        float Af = (float)a;

        unsigned cmask = 0;
        #pragma unroll
        for (int j = 0; j < 8; ++j) {
            float vv[4] = {v[j].x, v[j].y, v[j].z, v[j].w};
            #pragma unroll
            for (int c = 0; c < 4; ++c)
                if (vv[c] <= thresh) cmask |= 1u << (4 * j + c);
        }

        unsigned long long key = 0xFFFFFFFFFFFFFFFFull;
        while (true) {
            unsigned ball = __ballot_sync(0xFFFFFFFFu, cmask != 0);
            if (!ball) break;
            int leader = __ffs(ball) - 1;
            unsigned lm = __shfl_sync(0xFFFFFFFFu, cmask, leader);
            int bit = __ffs(lm) - 1;
            int k = 4 * (leader + 32 * (bit >> 2)) + (bit & 3);
            if (lane == leader) cmask &= cmask - 1;

            const float* er = E + (size_t)k * D_;
            double dot = 0.0;
            #pragma unroll
            for (int t = 0; t < 8; ++t)
                dot += (double)xr[t] * (double)er[lane + 32 * t];
            #pragma unroll
            for (int off = 16; off > 0; off >>= 1)
                dot += __shfl_xor_sync(0xFFFFFFFFu, dot, off);

            float Mf = (float)dot;
            float T  = Af + __ldg(&g_B[k]);   // fl32
            float ds = T - 2.0f * Mf;         // fl32
            unsigned long long kk =
                ((unsigned long long)order_f(ds) << 32) | (unsigned)k;
            if (kk < key) key = kk;
        }
        k_final = (int)(unsigned)key;
    }

    if (lane == 0) {
        g_idx[n] = k_final;
        atomicAdd(&g_counts[k_final], 1);
    }
}

// ---------------------------------------------------------
__global__ void __launch_bounds__(256, 1)
gather_kernel(const float* __restrict__ IN, const float* __restrict__ E,
              float* __restrict__ OUT) {
    extern __shared__ float fsm[];
    float* qs   = fsm;                          // [128][257]
    int*   sidx = (int*)(fsm + 128 * 257);
    float* red  = fsm + 128 * 257 + 128;

    const int tid = threadIdx.x;
    const int n0  = blockIdx.x * BT;

    if (tid < BT) sidx[tid] = g_idx[n0 + tid];
    __syncthreads();

    #pragma unroll 4
    for (int it = 0; it < BT; ++it)
        qs[it * 257 + tid] = E[(size_t)sidx[it] * D_ + tid];
    __syncthreads();

    const int b = n0 >> 10, hw0 = n0 & (HW_ - 1);
    const size_t base = (size_t)b * (D_ * HW_) + hw0;
    float lsum = 0.0f;
    #pragma unroll 4
    for (int it = 0; it < 128; ++it) {
        int j = it * 256 + tid;
        int d = j >> 7;
        int t = j & 127;
        size_t a = base + (size_t)d * HW_ + t;
        float x = IN[a];
        float q = qs[t * 257 + d];
        OUT[a] = q;
        float df = q - x;
        lsum += df * df;
    }
    red[tid] = lsum;
    __syncthreads();
    for (int s = 128; s > 0; s >>= 1) {
        if (tid < s) red[tid] += red[tid + s];
        __syncthreads();
    }
    if (tid == 0) g_partials[blockIdx.x] = red[0];
}

// ---------------------------------------------------------
__global__ void finalize_kernel(float* __restrict__ OUT, int out_size) {
    __shared__ float red[256];
    int tid = threadIdx.x;

    red[tid] = g_partials[tid];
    __syncthreads();
    for (int s = 128; s > 0; s >>= 1) {
        if (tid < s) red[tid] += red[tid + s];
        __syncthreads();
    }
    float loss = 1.25f * red[0] / (float)NELEM_;
    __syncthreads();

    float ps = 0.0f;
    for (int i = tid; i < K_; i += 256) {
        float p = (float)g_counts[i] / (float)N_;
        ps += p * logf(p + 1e-10f);
    }
    red[tid] = ps;
    __syncthreads();
    for (int s = 128; s > 0; s >>= 1) {
        if (tid < s) red[tid] += red[tid + s];
        __syncthreads();
    }
    if (tid == 0) {
        float perp = expf(-red[0]);
        if (out_size > NELEM_)     OUT[NELEM_]     = loss;
        if (out_size > NELEM_ + 1) OUT[NELEM_ + 1] = perp;
    }
}

// ---------------------------------------------------------
extern "C" void kernel_launch(void* const* d_in, const int* in_sizes, int n_in,
                              void* d_out, int out_size) {
    const float* IN = (const float*)d_in[0];
    const float* E  = (const float*)d_in[1];
    float* OUT = (float*)d_out;

    const int smemX = D_ * BT * (int)sizeof(unsigned short);         // 65536
    const int smemM = SMEM_MMA;                                      // 135168
    const int smemC = (128 * 257 + 128 + 256) * (int)sizeof(float);
    cudaFuncSetAttribute(xbf_kernel,      cudaFuncAttributeMaxDynamicSharedMemorySize, smemX);
    cudaFuncSetAttribute(dist_mma_kernel, cudaFuncAttributeMaxDynamicSharedMemorySize, smemM);
    cudaFuncSetAttribute(gather_kernel,   cudaFuncAttributeMaxDynamicSharedMemorySize, smemC);

    init_kernel<<<4, 256>>>();
    ebf_kernel<<<K_, 256>>>(E);
    enorm_kernel<<<K_, 256>>>(E);
    xbf_kernel<<<N_ / BT, 256, smemX>>>(IN);
    dist_mma_kernel<<<dim3(N_ / BT, K_ / BT), 256, smemM>>>();
    select_kernel<<<N_ / 8, 256>>>(IN, E);
    gather_kernel<<<N_ / BT, 256, smemC>>>(IN, E, OUT);
    finalize_kernel<<<1, 256>>>(OUT, out_size);
}